// round 6
// baseline (speedup 1.0000x reference)
#include <cuda_runtime.h>
#include <stdint.h>

typedef unsigned long long u64;

#define HID   256
#define HOR   30
#define NC    5
#define NROWS 32768
#define TILE  32
#define NTHR  256
#define RPW   4

// shared-const float offsets (after 2 activation buffers)
#define OFF_WIN1 0
#define OFF_BIN1 1792
#define OFF_BIN2 2048
#define OFF_LN1G 2304
#define OFF_LN1B 2560
#define OFF_BIH  2816
#define OFF_BHH  3584
#define OFF_LN2G 4352
#define OFF_LN2B 4608
#define OFF_BM1  4864
#define OFF_WM2  4992
#define OFF_BM2  5632
#define OFF_DT   5640
#define OFF_FEAT 5652
#define CONSTF   5920
#define SMEM_BYTES ((2*TILE*HID + CONSTF)*4)   // 65536 + 23680 = 89216

__device__ int g_cnt;
__device__ int g_fmt;
__device__ int g_active[NROWS];
// k-pair interleaved weights: wp[k2*ldw + c] = {w[2k2][c], w[2k2+1][c]}
__device__ u64 wih_p[128*768];
__device__ u64 whh_p[128*768];
__device__ u64 win2_p[128*256];
__device__ u64 wm1_p[128*128];

__device__ __forceinline__ void ffma2(u64 &d, u64 a, u64 b){
    asm("fma.rn.f32x2 %0, %1, %2, %0;" : "+l"(d) : "l"(a), "l"(b));
}
__device__ __forceinline__ void unpk(u64 v, float &lo, float &hi){
    unsigned a, b;
    asm("mov.b64 {%0, %1}, %2;" : "=r"(a), "=r"(b) : "l"(v));
    lo = __uint_as_float(a); hi = __uint_as_float(b);
}
__device__ __forceinline__ u64 pack2(float lo, float hi){
    u64 r;
    asm("mov.b64 %0, {%1, %2};" : "=l"(r) : "r"(__float_as_uint(lo)), "r"(__float_as_uint(hi)));
    return r;
}
__device__ __forceinline__ float mergef(u64 v){
    float lo, hi; unpk(v, lo, hi); return lo + hi;
}
__device__ __forceinline__ float wsum(float v){
    #pragma unroll
    for (int o = 16; o; o >>= 1) v += __shfl_xor_sync(0xffffffffu, v, o);
    return v;
}
__device__ __forceinline__ float sigf(float x){
    return __fdividef(1.0f, 1.0f + __expf(-x));
}
__device__ __forceinline__ float tanhf_(float x){
    return fmaf(2.0f, sigf(2.0f * x), -1.0f);
}

// ---- prep kernels ----
__global__ void k_detect(const unsigned* __restrict__ m){
    __shared__ int f8, ff;
    if (threadIdx.x == 0){ f8 = 0; ff = 0; g_cnt = 0; }
    __syncthreads();
    int a = 0, b = 0;
    for (int i = threadIdx.x; i < 8192; i += NTHR){
        unsigned w = m[i];
        if (w == 0x3F800000u) b = 1;
        else if (w > 1u)      a = 1;
    }
    if (a) atomicOr(&f8, 1);
    if (b) atomicOr(&ff, 1);
    __syncthreads();
    if (threadIdx.x == 0) g_fmt = ff ? 2 : (f8 ? 0 : 1);
}

__global__ void k_compact(const void* __restrict__ mask, int n){
    int i = blockIdx.x * blockDim.x + threadIdx.x;
    if (i >= n) return;
    int fmt = g_fmt;
    bool m;
    if (fmt == 0)      m = ((const unsigned char*)mask)[i] != 0;
    else if (fmt == 1) m = ((const int*)mask)[i] != 0;
    else               m = ((const float*)mask)[i] != 0.0f;
    if (m) g_active[atomicAdd(&g_cnt, 1)] = i;
}

__global__ void k_zero(float4* __restrict__ p, int n4){
    int i = blockIdx.x * blockDim.x + threadIdx.x;
    if (i < n4) p[i] = make_float4(0.f, 0.f, 0.f, 0.f);
}

__global__ void k_pack(const float* __restrict__ wih, const float* __restrict__ whh,
                       const float* __restrict__ win2, const float* __restrict__ wm1){
    int i = blockIdx.x * blockDim.x + threadIdx.x;
    if (i < 128*768){
        int k2 = i / 768, c = i % 768;
        wih_p[i] = pack2(wih[(2*k2)*768 + c], wih[(2*k2+1)*768 + c]);
        whh_p[i] = pack2(whh[(2*k2)*768 + c], whh[(2*k2+1)*768 + c]);
    }
    if (i < 128*256){
        int k2 = i / 256, c = i % 256;
        win2_p[i] = pack2(win2[(2*k2)*256 + c], win2[(2*k2+1)*256 + c]);
    }
    if (i < 128*128){
        int k2 = i / 128, c = i % 128;
        wm1_p[i] = pack2(wm1[(2*k2)*128 + c], wm1[(2*k2+1)*128 + c]);
    }
}

// ---- K-split GEMM core: 4 rows x 4 cols, acc.lo = even-k partial, acc.hi = odd-k ----
__device__ __forceinline__ void gemmks(u64 acc[RPW][4], const float* __restrict__ act,
                                       const u64* __restrict__ wp, int ldw){
    #pragma unroll 2
    for (int k2 = 0; k2 < 128; ++k2){
        const u64* w = wp + (size_t)k2 * ldw;
        ulonglong2 wa = *(const ulonglong2*)w;        // cols +0,+1
        ulonglong2 wb = *(const ulonglong2*)(w + 2);  // cols +2,+3
        u64 a0 = *(const u64*)(act + 2*k2);
        u64 a1 = *(const u64*)(act + 256 + 2*k2);
        u64 a2 = *(const u64*)(act + 512 + 2*k2);
        u64 a3 = *(const u64*)(act + 768 + 2*k2);
        ffma2(acc[0][0], a0, wa.x); ffma2(acc[0][1], a0, wa.y);
        ffma2(acc[0][2], a0, wb.x); ffma2(acc[0][3], a0, wb.y);
        ffma2(acc[1][0], a1, wa.x); ffma2(acc[1][1], a1, wa.y);
        ffma2(acc[1][2], a1, wb.x); ffma2(acc[1][3], a1, wb.y);
        ffma2(acc[2][0], a2, wa.x); ffma2(acc[2][1], a2, wa.y);
        ffma2(acc[2][2], a2, wb.x); ffma2(acc[2][3], a2, wb.y);
        ffma2(acc[3][0], a3, wa.x); ffma2(acc[3][1], a3, wa.y);
        ffma2(acc[3][2], a3, wb.x); ffma2(acc[3][3], a3, wb.y);
    }
}

__device__ __forceinline__ void initb(u64 acc[RPW][4], const float* __restrict__ b){
    u64 p[4];
    #pragma unroll
    for (int j = 0; j < 4; ++j) p[j] = (u64)__float_as_uint(b[j]);  // {bias, 0}
    #pragma unroll
    for (int r = 0; r < RPW; ++r)
        #pragma unroll
        for (int j = 0; j < 4; ++j) acc[r][j] = p[j];
}
__device__ __forceinline__ void initb2(u64 acc[RPW][4], const float* __restrict__ b1,
                                       const float* __restrict__ b2){
    u64 p[4];
    #pragma unroll
    for (int j = 0; j < 4; ++j) p[j] = (u64)__float_as_uint(b1[j] + b2[j]);
    #pragma unroll
    for (int r = 0; r < RPW; ++r)
        #pragma unroll
        for (int j = 0; j < 4; ++j) acc[r][j] = p[j];
}
__device__ __forceinline__ void mergeall(const u64 acc[RPW][4], float v[RPW][4]){
    #pragma unroll
    for (int r = 0; r < RPW; ++r)
        #pragma unroll
        for (int j = 0; j < 4; ++j) v[r][j] = mergef(acc[r][j]);
}

// store v (8 cols/lane) plain: cols c0..c0+3 and c0+128..c0+131
__device__ __forceinline__ void writeplain(float* __restrict__ aw, const float v[RPW][8], int c0){
    #pragma unroll
    for (int r = 0; r < RPW; ++r){
        *(float4*)(aw + r*HID + c0)       = make_float4(v[r][0], v[r][1], v[r][2], v[r][3]);
        *(float4*)(aw + r*HID + c0 + 128) = make_float4(v[r][4], v[r][5], v[r][6], v[r][7]);
    }
}

__device__ __forceinline__ void layernorm(float v[RPW][8], const float* __restrict__ g,
                                          const float* __restrict__ b, int c0){
    #pragma unroll
    for (int r = 0; r < RPW; ++r){
        float s = 0.f;
        #pragma unroll
        for (int j = 0; j < 8; ++j) s += v[r][j];
        float mu = wsum(s) * (1.0f/256.0f);
        float q = 0.f;
        #pragma unroll
        for (int j = 0; j < 8; ++j){ v[r][j] -= mu; q += v[r][j]*v[r][j]; }
        float iv = rsqrtf(wsum(q) * (1.0f/256.0f) + 1e-5f);
        #pragma unroll
        for (int j = 0; j < 8; ++j){
            int c = c0 + (j < 4 ? j : 124 + j);
            v[r][j] = v[r][j] * iv * g[c] + b[c];
        }
    }
}

// input_proj: feat[7] -> relu(LN(relu(feat@W1+b1)@W2+b2)); scratches xw
__device__ __forceinline__ void input_proj(float v[RPW][8], const float* __restrict__ feats,
        const float* __restrict__ sc, float* __restrict__ xw, int c0){
    float h1[RPW][8];
    #pragma unroll
    for (int r = 0; r < RPW; ++r){
        #pragma unroll
        for (int j = 0; j < 8; ++j){
            int c = c0 + (j < 4 ? j : 124 + j);
            float s = sc[OFF_BIN1 + c];
            #pragma unroll
            for (int k = 0; k < 7; ++k)
                s = fmaf(feats[r*8 + k], sc[OFF_WIN1 + k*HID + c], s);
            h1[r][j] = fmaxf(s, 0.f);
        }
    }
    __syncwarp();
    writeplain(xw, h1, c0);
    __syncwarp();
    #pragma unroll 1
    for (int cg = 0; cg < 2; ++cg){
        int cabs = c0 + cg*128;
        u64 acc[RPW][4];
        initb(acc, sc + OFF_BIN2 + cabs);
        gemmks(acc, xw, win2_p + cabs, 256);
        #pragma unroll
        for (int r = 0; r < RPW; ++r)
            #pragma unroll
            for (int j = 0; j < 4; ++j) v[r][cg*4 + j] = mergef(acc[r][j]);
    }
    layernorm(v, sc + OFF_LN1G, sc + OFF_LN1B, c0);
    #pragma unroll
    for (int r = 0; r < RPW; ++r)
        #pragma unroll
        for (int j = 0; j < 8; ++j) v[r][j] = fmaxf(v[r][j], 0.f);
}

__device__ __forceinline__ void cpyf(float* dst, const float* src, int n, int tid){
    for (int i = tid; i < n; i += NTHR) dst[i] = src[i];
}

// ---- main persistent kernel: 2 CTAs/SM ----
__global__ void __launch_bounds__(NTHR, 2)
k_main(const float* __restrict__ obs,
       const float* __restrict__ delta_table,
       const float* __restrict__ w_in1, const float* __restrict__ b_in1,
       const float* __restrict__ b_in2,
       const float* __restrict__ ln1g, const float* __restrict__ ln1b,
       const float* __restrict__ b_ih, const float* __restrict__ b_hh,
       const float* __restrict__ ln2g, const float* __restrict__ ln2b,
       const float* __restrict__ b_m1,
       const float* __restrict__ w_m2, const float* __restrict__ b_m2,
       float* __restrict__ out)
{
    int cnt = g_cnt;
    int base = blockIdx.x * TILE;
    if (base >= cnt) return;

    extern __shared__ float smemf[];
    float* xd = smemf;                 // [TILE][256] plain fp32
    float* hd = smemf + TILE*HID;      // [TILE][256]
    float* sc = smemf + 2*TILE*HID;    // consts

    int tid = threadIdx.x;
    cpyf(sc + OFF_WIN1, w_in1, 7*HID, tid);
    cpyf(sc + OFF_BIN1, b_in1, HID, tid);
    cpyf(sc + OFF_BIN2, b_in2, HID, tid);
    cpyf(sc + OFF_LN1G, ln1g, HID, tid);
    cpyf(sc + OFF_LN1B, ln1b, HID, tid);
    cpyf(sc + OFF_BIH,  b_ih, 3*HID, tid);
    cpyf(sc + OFF_BHH,  b_hh, 3*HID, tid);
    cpyf(sc + OFF_LN2G, ln2g, HID, tid);
    cpyf(sc + OFF_LN2B, ln2b, HID, tid);
    cpyf(sc + OFF_BM1,  b_m1, 128, tid);
    cpyf(sc + OFF_WM2,  w_m2, 640, tid);
    cpyf(sc + OFF_BM2,  b_m2, NC, tid);
    cpyf(sc + OFF_DT,   delta_table, NC*2, tid);
    __syncthreads();

    int lane = tid & 31, warp = tid >> 5;
    int wrow = warp * RPW;
    if (base + wrow >= cnt) return;

    int gi[RPW]; bool valid[RPW];
    #pragma unroll
    for (int r = 0; r < RPW; ++r){
        int idx = base + wrow + r;
        valid[r] = (idx < cnt);
        gi[r] = g_active[valid[r] ? idx : base];
    }

    float* feats = sc + OFF_FEAT + wrow*8;
    if (lane < 7*RPW){
        int r = lane / 7, k = lane % 7;
        feats[r*8 + k] = obs[(size_t)gi[r]*7 + k];
    }
    __syncwarp();

    const int c0 = lane * 4;
    float* xw = xd + wrow*HID;
    float* hw = hd + wrow*HID;
    const float* dt = sc + OFF_DT;

    float v[RPW][8];
    input_proj(v, feats, sc, xw, c0);   // h0 (== x at t=0)
    __syncwarp();
    writeplain(hw, v, c0);
    __syncwarp();

    for (int t = 0; t < HOR; ++t){
        if (t > 0) input_proj(v, feats, sc, xw, c0);
        __syncwarp();
        writeplain(xw, v, c0);
        __syncwarp();

        // gates, processed per 4-col group to bound register pressure
        #pragma unroll 1
        for (int cg = 0; cg < 2; ++cg){
            int cabs = c0 + cg*128;   // absolute col of this group's first element
            u64 acc[RPW][4];
            // r gate
            initb2(acc, sc + OFF_BIH + cabs, sc + OFF_BHH + cabs);
            gemmks(acc, xw, wih_p + cabs, 768);
            gemmks(acc, hw, whh_p + cabs, 768);
            float rr[RPW][4];
            mergeall(acc, rr);
            #pragma unroll
            for (int r = 0; r < RPW; ++r)
                #pragma unroll
                for (int j = 0; j < 4; ++j) rr[r][j] = sigf(rr[r][j]);
            // hn
            initb(acc, sc + OFF_BHH + 512 + cabs);
            gemmks(acc, hw, whh_p + 512 + cabs, 768);
            float hn[RPW][4];
            mergeall(acc, hn);
            // inn, then n
            initb(acc, sc + OFF_BIH + 512 + cabs);
            gemmks(acc, xw, wih_p + 512 + cabs, 768);
            float nn[RPW][4];
            #pragma unroll
            for (int r = 0; r < RPW; ++r)
                #pragma unroll
                for (int j = 0; j < 4; ++j)
                    nn[r][j] = tanhf_(fmaf(rr[r][j], hn[r][j], mergef(acc[r][j])));
            // z gate
            initb2(acc, sc + OFF_BIH + 256 + cabs, sc + OFF_BHH + 256 + cabs);
            gemmks(acc, xw, wih_p + 256 + cabs, 768);
            gemmks(acc, hw, whh_p + 256 + cabs, 768);
            #pragma unroll
            for (int r = 0; r < RPW; ++r)
                #pragma unroll
                for (int j = 0; j < 4; ++j){
                    float z = sigf(mergef(acc[r][j]));
                    float hv = hw[r*HID + cabs + j];   // FIXED: cabs is already absolute
                    v[r][cg*4 + j] = (1.0f - z) * nn[r][j] + z * hv;
                }
        }
        layernorm(v, sc + OFF_LN2G, sc + OFF_LN2B, c0);
        __syncwarp();
        writeplain(hw, v, c0);
        __syncwarp();

        // move head layer 1 (128 cols, lane owns c0..c0+3)
        u64 am[RPW][4];
        initb(am, sc + OFF_BM1 + c0);
        gemmks(am, hw, wm1_p + c0, 128);
        float mv[RPW][4];
        mergeall(am, mv);
        #pragma unroll
        for (int r = 0; r < RPW; ++r)
            #pragma unroll
            for (int j = 0; j < 4; ++j) mv[r][j] = fmaxf(mv[r][j], 0.f);

        // logits = m1 @ w_m2 + b_m2 (warp reduction over 128)
        float part[RPW][NC];
        #pragma unroll
        for (int r = 0; r < RPW; ++r)
            #pragma unroll
            for (int c = 0; c < NC; ++c) part[r][c] = 0.f;
        #pragma unroll
        for (int r = 0; r < RPW; ++r)
            #pragma unroll
            for (int j = 0; j < 4; ++j)
                #pragma unroll
                for (int c = 0; c < NC; ++c)
                    part[r][c] = fmaf(mv[r][j], sc[OFF_WM2 + (c0 + j)*NC + c], part[r][c]);
        #pragma unroll
        for (int off = 16; off; off >>= 1)
            #pragma unroll
            for (int r = 0; r < RPW; ++r)
                #pragma unroll
                for (int c = 0; c < NC; ++c)
                    part[r][c] += __shfl_xor_sync(0xffffffffu, part[r][c], off);
        #pragma unroll
        for (int r = 0; r < RPW; ++r)
            #pragma unroll
            for (int c = 0; c < NC; ++c) part[r][c] += sc[OFF_BM2 + c];

        // store logits
        #pragma unroll
        for (int r = 0; r < RPW; ++r){
            if (lane < NC && valid[r]){
                float vv = (lane == 0) ? part[r][0] :
                           (lane == 1) ? part[r][1] :
                           (lane == 2) ? part[r][2] :
                           (lane == 3) ? part[r][3] : part[r][4];
                out[(size_t)gi[r]*(HOR*NC) + t*NC + lane] = vv;
            }
        }

        // softmax -> expected delta -> feat update (cvf==1 for active rows)
        if (t + 1 < HOR){
            #pragma unroll
            for (int r = 0; r < RPW; ++r){
                float m = part[r][0];
                #pragma unroll
                for (int c = 1; c < NC; ++c) m = fmaxf(m, part[r][c]);
                float e[NC], s = 0.f;
                #pragma unroll
                for (int c = 0; c < NC; ++c){ e[c] = __expf(part[r][c] - m); s += e[c]; }
                float inv = __fdividef(1.0f, s);
                float dx = 0.f, dy = 0.f;
                #pragma unroll
                for (int c = 0; c < NC; ++c){
                    dx = fmaf(e[c], dt[2*c],   dx);
                    dy = fmaf(e[c], dt[2*c+1], dy);
                }
                dx *= inv; dy *= inv;
                if (lane == 0){
                    feats[r*8+0] = fminf(fmaxf(feats[r*8+0] + dx, 0.f), 1.f);
                    feats[r*8+1] = fminf(fmaxf(feats[r*8+1] + dy, 0.f), 1.f);
                }
            }
            __syncwarp();
        }
    }
}

extern "C" void kernel_launch(void* const* d_in, const int* in_sizes, int n_in,
                              void* d_out, int out_size) {
    const float* obs  = (const float*)d_in[0];
    const void*  mask = d_in[1];
    const float* dt   = (const float*)d_in[2];
    const float* w_in1 = (const float*)d_in[3];
    const float* b_in1 = (const float*)d_in[4];
    const float* w_in2 = (const float*)d_in[5];
    const float* b_in2 = (const float*)d_in[6];
    const float* ln1g  = (const float*)d_in[7];
    const float* ln1b  = (const float*)d_in[8];
    const float* w_ih  = (const float*)d_in[9];
    const float* b_ih  = (const float*)d_in[10];
    const float* w_hh  = (const float*)d_in[11];
    const float* b_hh  = (const float*)d_in[12];
    const float* ln2g  = (const float*)d_in[13];
    const float* ln2b  = (const float*)d_in[14];
    const float* w_m1  = (const float*)d_in[15];
    const float* b_m1  = (const float*)d_in[16];
    const float* w_m2  = (const float*)d_in[17];
    const float* b_m2  = (const float*)d_in[18];
    float* out = (float*)d_out;

    static int attr_set = 0;
    if (!attr_set){
        cudaFuncSetAttribute(k_main, cudaFuncAttributeMaxDynamicSharedMemorySize, SMEM_BYTES);
        attr_set = 1;
    }

    k_detect<<<1, NTHR>>>((const unsigned*)mask);
    k_compact<<<(NROWS + NTHR - 1)/NTHR, NTHR>>>(mask, NROWS);
    k_pack<<<(128*768 + NTHR - 1)/NTHR, NTHR>>>(w_ih, w_hh, w_in2, w_m1);
    k_zero<<<(out_size/4 + NTHR - 1)/NTHR, NTHR>>>((float4*)out, out_size/4);
    k_main<<<NROWS/TILE, NTHR, SMEM_BYTES>>>(
        obs, dt, w_in1, b_in1, b_in2, ln1g, ln1b,
        b_ih, b_hh, ln2g, ln2b, b_m1, w_m2, b_m2, out);
}